// round 17
// baseline (speedup 1.0000x reference)
#include <cuda_runtime.h>
#include <cuda_fp16.h>
#include <math.h>
#include <stdint.h>

#define N_NODES 20000
#define N_EDGES 320000
#define NE_TOT  (N_EDGES + N_NODES)   /* 340000 incl self loops */
#define IN_CH   512
#define HID     128
#define HEADS   4
#define OUT_CH  256
#define L1_F    (HEADS * HID)         /* 512 */

#define A1_OFF  (N_NODES * OUT_CH)            /* 5,120,000 */
#define A2_OFF  (A1_OFF + NE_TOT * HEADS)     /* 6,480,000 */

#define CHUNK0  10112                          /* 79 * 128 */
#define CHUNK1  (N_NODES - CHUNK0)             /* 9888 */

/* ------------------------- scratch (device globals) ------------------------- */
__device__ __half g_h1f[(size_t)N_NODES * L1_F];   /* h1, fp16 */
__device__ __half g_h2f[(size_t)N_NODES * OUT_CH]; /* h2, fp16 */
__device__ __half g_xf[(size_t)N_NODES * IN_CH];   /* x,  fp16 */
__device__ __half g_w1h[L1_F * IN_CH];             /* transposed [N][K], fp16 */
__device__ __half g_w2h[OUT_CH * L1_F];
__device__ __half g_a1f[(size_t)N_NODES * L1_F];   /* agg1, fp16 */
__device__ float g_as1[N_NODES * HEADS];
__device__ float g_ad1[N_NODES * HEADS];
__device__ float g_as2[N_NODES];
__device__ float g_ad2[N_NODES];
__device__ float g_vbuf[(size_t)NE_TOT * HEADS];   /* layer1: [edge][head] f4 */
__device__ int   g_counts[N_NODES];
__device__ int   g_cursor[N_NODES];
__device__ int   g_rowptr[N_NODES + 1];
__device__ int   g_esrc[NE_TOT];
__device__ int   g_eorig[NE_TOT];

/* ------------------------- helpers ------------------------- */
__device__ __forceinline__ uint32_t smem_u32(const void* p) {
    uint32_t a;
    asm("{ .reg .u64 t; cvta.to.shared.u64 t, %1; cvt.u32.u64 %0, t; }" : "=r"(a) : "l"(p));
    return a;
}
__device__ __forceinline__ void ldsm_x4(uint32_t& r0, uint32_t& r1, uint32_t& r2,
                                        uint32_t& r3, uint32_t addr) {
    asm volatile("ldmatrix.sync.aligned.m8n8.x4.shared.b16 {%0,%1,%2,%3}, [%4];"
                 : "=r"(r0), "=r"(r1), "=r"(r2), "=r"(r3) : "r"(addr));
}
__device__ __forceinline__ void mma_f16(float* d, const uint32_t* a, const uint32_t* b) {
    asm volatile("mma.sync.aligned.m16n8k16.row.col.f32.f16.f16.f32 "
                 "{%0,%1,%2,%3}, {%4,%5,%6,%7}, {%8,%9}, {%0,%1,%2,%3};"
                 : "+f"(d[0]), "+f"(d[1]), "+f"(d[2]), "+f"(d[3])
                 : "r"(a[0]), "r"(a[1]), "r"(a[2]), "r"(a[3]), "r"(b[0]), "r"(b[1]));
}
__device__ __forceinline__ void cpa16(uint32_t dst, const void* src) {
    asm volatile("cp.async.cg.shared.global [%0], [%1], 16;" :: "r"(dst), "l"(src));
}
#define CP_COMMIT() asm volatile("cp.async.commit_group;" ::: "memory")
#define CP_WAIT0()  asm volatile("cp.async.wait_group 0;" ::: "memory")

__device__ __forceinline__ float lrelu(float v) { return v > 0.f ? v : 0.2f * v; }

/* ------------------------- CSR construction ------------------------- */
__device__ __forceinline__ void edge_nodes(const int* __restrict__ ei, int e,
                                           int& src, int& dst) {
    if (e < N_EDGES) { src = ei[e]; dst = ei[N_EDGES + e]; }
    else             { src = dst = e - N_EDGES; }
}

__global__ void zero_counts() {
    int i = blockIdx.x * blockDim.x + threadIdx.x;
    if (i < N_NODES) { g_counts[i] = 0; g_cursor[i] = 0; }
}

__global__ void count_deg(const int* __restrict__ ei) {
    int e = blockIdx.x * blockDim.x + threadIdx.x;
    if (e >= NE_TOT) return;
    int src, dst;
    edge_nodes(ei, e, src, dst);
    atomicAdd(&g_counts[dst], 1);
}

__global__ void scan_rowptr() {
    __shared__ int wsum[32];
    __shared__ int s_carry;
    int tid = threadIdx.x, lane = tid & 31, wid = tid >> 5;
    if (tid == 0) { g_rowptr[0] = 0; s_carry = 0; }
    __syncthreads();
    for (int base = 0; base < N_NODES; base += 1024) {
        int i = base + tid;
        int v = (i < N_NODES) ? g_counts[i] : 0;
        int x = v;
#pragma unroll
        for (int o = 1; o < 32; o <<= 1) {
            int t = __shfl_up_sync(0xFFFFFFFFu, x, o);
            if (lane >= o) x += t;
        }
        if (lane == 31) wsum[wid] = x;
        __syncthreads();
        if (wid == 0) {
            int s = wsum[lane];
#pragma unroll
            for (int o = 1; o < 32; o <<= 1) {
                int t = __shfl_up_sync(0xFFFFFFFFu, s, o);
                if (lane >= o) s += t;
            }
            wsum[lane] = s;
        }
        __syncthreads();
        int inc = x + (wid > 0 ? wsum[wid - 1] : 0) + s_carry;
        if (i < N_NODES) g_rowptr[i + 1] = inc;
        __syncthreads();
        if (tid == 1023) s_carry = inc;
        __syncthreads();
    }
}

__global__ void scatter_edges(const int* __restrict__ ei) {
    int e = blockIdx.x * blockDim.x + threadIdx.x;
    if (e >= NE_TOT) return;
    int src, dst;
    edge_nodes(ei, e, src, dst);
    int pos = g_rowptr[dst] + atomicAdd(&g_cursor[dst], 1);
    g_esrc[pos]  = src;
    g_eorig[pos] = e;
}

/* ------------------------- fp32 -> fp16 converts ------------------------- */
__global__ void cvt_fp32(const float* __restrict__ in, __half* __restrict__ o, int n) {
    int i = blockIdx.x * blockDim.x + threadIdx.x;
    if (i >= n) return;
    o[i] = __float2half_rn(in[i]);
}

/* W [K][N] -> out [N][K] fp16 */
__global__ void cvt_w_t(const float* __restrict__ W,
                        __half* __restrict__ t, int K, int N) {
    int i = blockIdx.x * blockDim.x + threadIdx.x;
    if (i >= K * N) return;
    int k = i / N, n = i % N;
    t[n * K + k] = __float2half_rn(W[i]);
}

/* ------------------------- HMMA fp16 GEMM -------------------------
   C[M,N] = A*B^T; A fp16 [M,K], B fp16 [N,K]. K=512.
   CTA tile 128x128, 8 warps, 2-buffer cp.async, wait0. fp16 output. */
#define KSTAGES (512 / 16)    /* 32 */
#define SROW    24

__global__ __launch_bounds__(256)
void gemm_hmma(const __half* __restrict__ A, const __half* __restrict__ B,
               __half* __restrict__ Cf, int M, int N) {
    __shared__ __align__(16) __half sA[2][128][SROW];
    __shared__ __align__(16) __half sB[2][128][SROW];

    int tid = threadIdx.x, wid = tid >> 5, lane = tid & 31;
    int m0 = blockIdx.y * 128, n0 = blockIdx.x * 128;
    int wm = (wid >> 1) * 32;
    int wn = (wid & 1) * 64;

    int prow = tid >> 1, pseg = tid & 1;
    int agr = m0 + prow; if (agr >= M) agr = M - 1;
    const __half* pA = A + (size_t)agr * 512 + pseg * 8;
    const __half* pB = B + (size_t)(n0 + prow) * 512 + pseg * 8;
    uint32_t dA[2], dB[2];
#pragma unroll
    for (int b = 0; b < 2; b++) {
        dA[b] = smem_u32(&sA[b][prow][pseg * 8]);
        dB[b] = smem_u32(&sB[b][prow][pseg * 8]);
    }

    int a_row = (lane & 15), a_k = (lane >> 4) * 8;
    int b_nrow = ((lane >> 4) << 3) + (lane & 7), b_k = ((lane >> 3) & 1) * 8;
    uint32_t a_base = smem_u32(&sA[0][wm + a_row][a_k]);
    uint32_t b_base = smem_u32(&sB[0][wn + b_nrow][b_k]);
    const uint32_t BUF = 128 * SROW * 2;

    float acc[2][8][4];
#pragma unroll
    for (int i = 0; i < 2; i++)
#pragma unroll
        for (int j = 0; j < 8; j++)
#pragma unroll
            for (int q = 0; q < 4; q++) acc[i][j][q] = 0.f;

    cpa16(dA[0], pA);
    cpa16(dB[0], pB);
    CP_COMMIT();
    CP_WAIT0();
    __syncthreads();

    for (int t = 0; t < KSTAGES; t++) {
        int buf = t & 1;
        if (t + 1 < KSTAGES) {
            int nb = (t + 1) & 1, ko = (t + 1) * 16;
            cpa16(dA[nb], pA + ko);
            cpa16(dB[nb], pB + ko);
            CP_COMMIT();
        }

        uint32_t af[2][4];
#pragma unroll
        for (int ma = 0; ma < 2; ma++)
            ldsm_x4(af[ma][0], af[ma][1], af[ma][2], af[ma][3],
                    a_base + buf * BUF + ma * 16 * SROW * 2);
        uint32_t bf[4][4];
#pragma unroll
        for (int g = 0; g < 4; g++)
            ldsm_x4(bf[g][0], bf[g][1], bf[g][2], bf[g][3],
                    b_base + buf * BUF + g * 16 * SROW * 2);

#pragma unroll
        for (int ma = 0; ma < 2; ma++)
#pragma unroll
            for (int g = 0; g < 4; g++)
#pragma unroll
                for (int h = 0; h < 2; h++)
                    mma_f16(acc[ma][g * 2 + h], af[ma], &bf[g][h * 2]);

        CP_WAIT0();
        __syncthreads();
    }

    int lg = lane >> 2, lt = lane & 3;
#pragma unroll
    for (int ma = 0; ma < 2; ma++) {
        int mrow0 = m0 + wm + ma * 16 + lg;
#pragma unroll
        for (int nb = 0; nb < 8; nb++) {
            int n = n0 + wn + nb * 8 + lt * 2;
            float* d = acc[ma][nb];
            if (mrow0 < M)
                *(__half2*)(Cf + (size_t)mrow0 * N + n) = __floats2half2_rn(d[0], d[1]);
            if (mrow0 + 8 < M)
                *(__half2*)(Cf + (size_t)(mrow0 + 8) * N + n) = __floats2half2_rn(d[2], d[3]);
        }
    }
}

/* ------------------------- attention coefficients (fp16 h, chunked) -------- */
template <int H, int C>
__global__ void attn_coef(const __half* __restrict__ h,
                          const float* __restrict__ a_src,
                          const float* __restrict__ a_dst,
                          float* __restrict__ as, float* __restrict__ ad,
                          int n0, int ncount) {
    int gw = (blockIdx.x * blockDim.x + threadIdx.x) >> 5;
    int lane = threadIdx.x & 31;
    if (gw >= ncount * H) return;
    int n = n0 + gw / H, hh = gw % H;
    const __half2* hp = (const __half2*)(h + (size_t)n * (H * C) + hh * C);
    const float* sp = a_src + hh * C;
    const float* dp = a_dst + hh * C;
    float s = 0.f, d = 0.f;
#pragma unroll
    for (int r = 0; r < C / 64; r++) {
        int c2 = lane + 32 * r;
        float2 f = __half22float2(hp[c2]);
        s += f.x * sp[c2 * 2] + f.y * sp[c2 * 2 + 1];
        d += f.x * dp[c2 * 2] + f.y * dp[c2 * 2 + 1];
    }
#pragma unroll
    for (int o = 16; o; o >>= 1) {
        s += __shfl_xor_sync(0xFFFFFFFFu, s, o);
        d += __shfl_xor_sync(0xFFFFFFFFu, d, o);
    }
    if (lane == 0) { as[n * H + hh] = s; ad[n * H + hh] = d; }
}

/* ------------------------- layer-1 fused softmax+aggregate: warp per dst ---- */
__global__ __launch_bounds__(256)
void fused_agg_mh(const float* __restrict__ as, const float* __restrict__ ad,
                  const __half* __restrict__ hf, const float* __restrict__ bias,
                  float* __restrict__ alpha_out, __half* __restrict__ of16) {
    int gw = (blockIdx.x * blockDim.x + threadIdx.x) >> 5;
    int lane = threadIdx.x & 31;
    if (gw >= N_NODES) return;
    int dst = gw;
    int beg = g_rowptr[dst], end = g_rowptr[dst + 1];
    float4 adv = *(const float4*)(ad + dst * 4);
    float4* vb = (float4*)g_vbuf;

    float4 mx = make_float4(-1e30f, -1e30f, -1e30f, -1e30f);
    for (int i = beg + lane; i < end; i += 32) {
        float4 a4 = *(const float4*)(as + g_esrc[i] * 4);
        float4 v;
        v.x = lrelu(a4.x + adv.x);
        v.y = lrelu(a4.y + adv.y);
        v.z = lrelu(a4.z + adv.z);
        v.w = lrelu(a4.w + adv.w);
        vb[i] = v;
        mx.x = fmaxf(mx.x, v.x); mx.y = fmaxf(mx.y, v.y);
        mx.z = fmaxf(mx.z, v.z); mx.w = fmaxf(mx.w, v.w);
    }
#pragma unroll
    for (int o = 16; o; o >>= 1) {
        mx.x = fmaxf(mx.x, __shfl_xor_sync(0xFFFFFFFFu, mx.x, o));
        mx.y = fmaxf(mx.y, __shfl_xor_sync(0xFFFFFFFFu, mx.y, o));
        mx.z = fmaxf(mx.z, __shfl_xor_sync(0xFFFFFFFFu, mx.z, o));
        mx.w = fmaxf(mx.w, __shfl_xor_sync(0xFFFFFFFFu, mx.w, o));
    }

    float4 sm = make_float4(0.f, 0.f, 0.f, 0.f);
    for (int i = beg + lane; i < end; i += 32) {
        float4 v = vb[i];
        sm.x += __expf(v.x - mx.x); sm.y += __expf(v.y - mx.y);
        sm.z += __expf(v.z - mx.z); sm.w += __expf(v.w - mx.w);
    }
#pragma unroll
    for (int o = 16; o; o >>= 1) {
        sm.x += __shfl_xor_sync(0xFFFFFFFFu, sm.x, o);
        sm.y += __shfl_xor_sync(0xFFFFFFFFu, sm.y, o);
        sm.z += __shfl_xor_sync(0xFFFFFFFFu, sm.z, o);
        sm.w += __shfl_xor_sync(0xFFFFFFFFu, sm.w, o);
    }

    int hsel = lane >> 3;
    float mxa[4] = { mx.x, mx.y, mx.z, mx.w };
    float sma[4] = { sm.x, sm.y, sm.z, sm.w };
    float mxh = mxa[hsel];
    float invh = 1.f / sma[hsel];
    const float* vbh = (const float*)g_vbuf + hsel;

    float acc[16];
#pragma unroll
    for (int j = 0; j < 16; j++) acc[j] = 0.f;

    int i = beg;
    int eo = g_eorig[i];
    float vh = vbh[(size_t)i * 4];
    uint4 u0, u1;
    {
        const uint4* hp = (const uint4*)(hf + (size_t)g_esrc[i] * 512 + lane * 16);
        u0 = hp[0]; u1 = hp[1];
    }
    for (;;) {
        int inext = i + 1;
        bool more = inext < end;
        int eo2 = 0;
        float vh2 = 0.f;
        uint4 v0, v1;
        if (more) {
            eo2 = g_eorig[inext];
            vh2 = vbh[(size_t)inext * 4];
            const uint4* hp2 = (const uint4*)(hf + (size_t)g_esrc[inext] * 512 + lane * 16);
            v0 = hp2[0]; v1 = hp2[1];
        }
        float a = __expf(vh - mxh) * invh;
        if ((lane & 7) == 0) alpha_out[eo * 4 + hsel] = a;
        const uint32_t* uu = (const uint32_t*)&u0;
#pragma unroll
        for (int q = 0; q < 4; q++) {
            float2 f = __half22float2(*(const __half2*)&uu[q]);
            acc[q * 2 + 0] += a * f.x;
            acc[q * 2 + 1] += a * f.y;
        }
        const uint32_t* uv = (const uint32_t*)&u1;
#pragma unroll
        for (int q = 0; q < 4; q++) {
            float2 f = __half22float2(*(const __half2*)&uv[q]);
            acc[8 + q * 2 + 0] += a * f.x;
            acc[8 + q * 2 + 1] += a * f.y;
        }
        if (!more) break;
        eo = eo2; vh = vh2; u0 = v0; u1 = v1;
        i = inext;
    }

    const float* bp = bias + lane * 16;
    __half2 ho[8];
#pragma unroll
    for (int q = 0; q < 8; q++) {
        float o0 = acc[q * 2 + 0] + bp[q * 2 + 0];
        float o1 = acc[q * 2 + 1] + bp[q * 2 + 1];
        o0 = o0 > 0.f ? o0 : expm1f(o0);
        o1 = o1 > 0.f ? o1 : expm1f(o1);
        ho[q] = __floats2half2_rn(o0, o1);
    }
    uint4* op = (uint4*)(of16 + (size_t)dst * 512 + lane * 16);
    op[0] = *(uint4*)&ho[0];
    op[1] = *(uint4*)&ho[4];
}

/* ------------------------- layer-2 fused softmax+aggregate: warp per dst ----
   One uint4 (8 fp16 channels) per lane per edge: full 512B row per warp. */
__global__ __launch_bounds__(256)
void fused_agg2(const float* __restrict__ as, const float* __restrict__ ad,
                const __half* __restrict__ hf, const float* __restrict__ bias,
                float* __restrict__ alpha_out, float* __restrict__ aggout) {
    int gw = (blockIdx.x * blockDim.x + threadIdx.x) >> 5;
    int lane = threadIdx.x & 31;
    if (gw >= N_NODES) return;
    int dst = gw;
    int beg = g_rowptr[dst], end = g_rowptr[dst + 1];
    float adv = ad[dst];
    float* vb = g_vbuf;

    float mx = -1e30f;
    for (int i = beg + lane; i < end; i += 32) {
        float v = lrelu(as[g_esrc[i]] + adv);
        vb[i] = v;
        mx = fmaxf(mx, v);
    }
#pragma unroll
    for (int o = 16; o; o >>= 1) mx = fmaxf(mx, __shfl_xor_sync(0xFFFFFFFFu, mx, o));

    float sm = 0.f;
    for (int i = beg + lane; i < end; i += 32) sm += __expf(vb[i] - mx);
#pragma unroll
    for (int o = 16; o; o >>= 1) sm += __shfl_xor_sync(0xFFFFFFFFu, sm, o);
    float inv = 1.f / sm;

    float acc[8];
#pragma unroll
    for (int j = 0; j < 8; j++) acc[j] = 0.f;

    int i = beg;
    int eo = g_eorig[i];
    float vv = vb[i];
    uint4 u0;
    {
        const uint4* hp = (const uint4*)(hf + (size_t)g_esrc[i] * 256 + lane * 8);
        u0 = hp[0];
    }
    for (;;) {
        int inext = i + 1;
        bool more = inext < end;
        int eo2 = 0;
        float vv2 = 0.f;
        uint4 v0;
        if (more) {
            eo2 = g_eorig[inext];
            vv2 = vb[inext];
            v0 = *(const uint4*)(hf + (size_t)g_esrc[inext] * 256 + lane * 8);
        }
        float a = __expf(vv - mx) * inv;
        if (lane == 0) alpha_out[eo] = a;
        const uint32_t* uu = (const uint32_t*)&u0;
#pragma unroll
        for (int q = 0; q < 4; q++) {
            float2 f = __half22float2(*(const __half2*)&uu[q]);
            acc[q * 2 + 0] += a * f.x;
            acc[q * 2 + 1] += a * f.y;
        }
        if (!more) break;
        eo = eo2; vv = vv2; u0 = v0;
        i = inext;
    }

    const float* bp = bias + lane * 8;
    float* op = aggout + (size_t)dst * 256 + lane * 8;
    float4 o0 = make_float4(acc[0] + bp[0], acc[1] + bp[1], acc[2] + bp[2], acc[3] + bp[3]);
    float4 o1 = make_float4(acc[4] + bp[4], acc[5] + bp[5], acc[6] + bp[6], acc[7] + bp[7]);
    *(float4*)op       = o0;
    *(float4*)(op + 4) = o1;
}

/* ------------------------- launch ------------------------- */
extern "C" void kernel_launch(void* const* d_in, const int* in_sizes, int n_in,
                              void* d_out, int out_size) {
    const float* x      = (const float*)d_in[0];
    const int*   ei     = (const int*)  d_in[1];
    const float* W1     = (const float*)d_in[2];
    const float* a_src1 = (const float*)d_in[3];
    const float* a_dst1 = (const float*)d_in[4];
    const float* b1     = (const float*)d_in[5];
    const float* W2     = (const float*)d_in[6];
    const float* a_src2 = (const float*)d_in[7];
    const float* a_dst2 = (const float*)d_in[8];
    const float* b2     = (const float*)d_in[9];
    float* out = (float*)d_out;

    float *as1, *ad1, *as2, *ad2;
    __half *h1f, *h2f, *xf, *w1h, *w2h, *a1f;
    cudaGetSymbolAddress((void**)&h1f,  g_h1f);
    cudaGetSymbolAddress((void**)&h2f,  g_h2f);
    cudaGetSymbolAddress((void**)&as1,  g_as1);
    cudaGetSymbolAddress((void**)&ad1,  g_ad1);
    cudaGetSymbolAddress((void**)&as2,  g_as2);
    cudaGetSymbolAddress((void**)&ad2,  g_ad2);
    cudaGetSymbolAddress((void**)&xf,   g_xf);
    cudaGetSymbolAddress((void**)&w1h,  g_w1h);
    cudaGetSymbolAddress((void**)&w2h,  g_w2h);
    cudaGetSymbolAddress((void**)&a1f,  g_a1f);

    static cudaStream_t s2 = nullptr;
    static cudaEvent_t evF = nullptr, evJ = nullptr, ev1 = nullptr, evA = nullptr,
                       ev2 = nullptr, evB = nullptr;
    if (!s2) {
        cudaStreamCreateWithFlags(&s2, cudaStreamNonBlocking);
        cudaEventCreateWithFlags(&evF, cudaEventDisableTiming);
        cudaEventCreateWithFlags(&evJ, cudaEventDisableTiming);
        cudaEventCreateWithFlags(&ev1, cudaEventDisableTiming);
        cudaEventCreateWithFlags(&evA, cudaEventDisableTiming);
        cudaEventCreateWithFlags(&ev2, cudaEventDisableTiming);
        cudaEventCreateWithFlags(&evB, cudaEventDisableTiming);
    }

    /* fork stream: CSR build + W2 convert */
    cudaEventRecord(evF, 0);
    cudaStreamWaitEvent(s2, evF, 0);
    zero_counts<<<(N_NODES + 255) / 256, 256, 0, s2>>>();
    count_deg<<<(NE_TOT + 255) / 256, 256, 0, s2>>>(ei);
    scan_rowptr<<<1, 1024, 0, s2>>>();
    scatter_edges<<<(NE_TOT + 255) / 256, 256, 0, s2>>>(ei);
    cvt_w_t<<<(L1_F * OUT_CH + 255) / 256, 256, 0, s2>>>(W2, w2h, L1_F, OUT_CH);
    cudaEventRecord(evJ, s2);

    /* main: converts, then layer-1 GEMM in 2 chunks, attn overlapped */
    cvt_fp32<<<(N_NODES * IN_CH + 255) / 256, 256>>>(x, xf, N_NODES * IN_CH);
    cvt_w_t<<<(IN_CH * L1_F + 255) / 256, 256>>>(W1, w1h, IN_CH, L1_F);

    gemm_hmma<<<dim3(L1_F / 128, CHUNK0 / 128), 256>>>(xf, w1h, h1f, CHUNK0, L1_F);
    cudaEventRecord(ev1, 0);
    cudaStreamWaitEvent(s2, ev1, 0);
    attn_coef<HEADS, HID><<<(CHUNK0 * HEADS + 7) / 8, 256, 0, s2>>>(
        h1f, a_src1, a_dst1, as1, ad1, 0, CHUNK0);
    cudaEventRecord(evA, s2);

    gemm_hmma<<<dim3(L1_F / 128, (CHUNK1 + 127) / 128), 256>>>(
        xf + (size_t)CHUNK0 * IN_CH, w1h, h1f + (size_t)CHUNK0 * L1_F, CHUNK1, L1_F);
    attn_coef<HEADS, HID><<<(CHUNK1 * HEADS + 7) / 8, 256>>>(
        h1f, a_src1, a_dst1, as1, ad1, CHUNK0, CHUNK1);

    /* join: CSR + chunk-0 attn */
    cudaStreamWaitEvent(0, evJ, 0);
    cudaStreamWaitEvent(0, evA, 0);
    fused_agg_mh<<<(N_NODES + 7) / 8, 256>>>(as1, ad1, h1f, b1, out + A1_OFF, a1f);

    /* layer 2: GEMM in 2 chunks, attn overlapped */
    gemm_hmma<<<dim3(OUT_CH / 128, CHUNK0 / 128), 256>>>(a1f, w2h, h2f, CHUNK0, OUT_CH);
    cudaEventRecord(ev2, 0);
    cudaStreamWaitEvent(s2, ev2, 0);
    attn_coef<1, OUT_CH><<<(CHUNK0 + 7) / 8, 256, 0, s2>>>(
        h2f, a_src2, a_dst2, as2, ad2, 0, CHUNK0);
    cudaEventRecord(evB, s2);

    gemm_hmma<<<dim3(OUT_CH / 128, (CHUNK1 + 127) / 128), 256>>>(
        a1f + (size_t)CHUNK0 * L1_F, w2h, h2f + (size_t)CHUNK0 * OUT_CH, CHUNK1, OUT_CH);
    attn_coef<1, OUT_CH><<<(CHUNK1 + 7) / 8, 256>>>(
        h2f, a_src2, a_dst2, as2, ad2, CHUNK0, CHUNK1);

    cudaStreamWaitEvent(0, evB, 0);
    fused_agg2<<<(N_NODES + 7) / 8, 256>>>(as2, ad2, h2f, b2, out + A2_OFF, out);
}